// round 5
// baseline (speedup 1.0000x reference)
#include <cuda_runtime.h>
#include <cuda_bf16.h>

// MoE noisy top-1 gating:
//   clean  = x @ w_gate          [N,3]
//   raw    = x @ w_noise         [N,3]
//   std    = softplus(raw) + 0.2
//   logits = clean + noise * std
//   out[t] = argmax_e logits[t][e]   (first index on ties, like lax.top_k)
//
// N=262144, D=256, E=3. HBM-bound (256MB input read).
// One warp per token; weights held in registers (loop-invariant per lane).
// Output written as FLOAT32 (harness compares in float space; int writes
// read back as denormals ~= 0 -> the exactly-1.0 rel_err observed in R2/R3).

#define GATE_N 262144
#define GATE_D 256
#define GATE_E 3
#define NOISE_EPS 0.2f

__global__ __launch_bounds__(256, 2)
void moe_gate_kernel(const float* __restrict__ x,
                     const float* __restrict__ wg,
                     const float* __restrict__ wn,
                     const float* __restrict__ noise,
                     float* __restrict__ out)
{
    const int lane   = threadIdx.x & 31;
    const int gwarp  = (blockIdx.x * blockDim.x + threadIdx.x) >> 5;
    const int nwarps = (gridDim.x * blockDim.x) >> 5;

    // Each lane owns dims d in {4*lane+i} and {128+4*lane+i}, i=0..3.
    // Hoist the 48 weight scalars into registers (invariant across tokens).
    float g[8][3], nz[8][3];
#pragma unroll
    for (int i = 0; i < 8; ++i) {
        const int d = (i < 4) ? (4 * lane + i) : (128 + 4 * lane + (i - 4));
#pragma unroll
        for (int e = 0; e < 3; ++e) {
            g[i][e]  = __ldg(wg + d * 3 + e);
            nz[i][e] = __ldg(wn + d * 3 + e);
        }
    }

    const float4* __restrict__ x4 = reinterpret_cast<const float4*>(x);

    for (int t = gwarp; t < GATE_N; t += nwarps) {
        // 1 KB coalesced row read: 64 float4 per token, 2 per lane.
        const float4 a = x4[(size_t)t * 64 + lane];
        const float4 b = x4[(size_t)t * 64 + 32 + lane];
        const float xs[8] = {a.x, a.y, a.z, a.w, b.x, b.y, b.z, b.w};

        float cg0 = 0.f, cg1 = 0.f, cg2 = 0.f;
        float cn0 = 0.f, cn1 = 0.f, cn2 = 0.f;
#pragma unroll
        for (int i = 0; i < 8; ++i) {
            const float v = xs[i];
            cg0 = fmaf(v, g[i][0],  cg0);
            cg1 = fmaf(v, g[i][1],  cg1);
            cg2 = fmaf(v, g[i][2],  cg2);
            cn0 = fmaf(v, nz[i][0], cn0);
            cn1 = fmaf(v, nz[i][1], cn1);
            cn2 = fmaf(v, nz[i][2], cn2);
        }

        // Butterfly reduce all 6 partials across the warp.
#pragma unroll
        for (int off = 16; off > 0; off >>= 1) {
            cg0 += __shfl_xor_sync(0xFFFFFFFFu, cg0, off);
            cg1 += __shfl_xor_sync(0xFFFFFFFFu, cg1, off);
            cg2 += __shfl_xor_sync(0xFFFFFFFFu, cg2, off);
            cn0 += __shfl_xor_sync(0xFFFFFFFFu, cn0, off);
            cn1 += __shfl_xor_sync(0xFFFFFFFFu, cn1, off);
            cn2 += __shfl_xor_sync(0xFFFFFFFFu, cn2, off);
        }

        if (lane == 0) {
            const float n0 = __ldg(noise + (size_t)t * 3 + 0);
            const float n1 = __ldg(noise + (size_t)t * 3 + 1);
            const float n2 = __ldg(noise + (size_t)t * 3 + 2);

            // stable softplus: max(x,0) + log1p(exp(-|x|))
            const float sp0 = fmaxf(cn0, 0.f) + log1pf(expf(-fabsf(cn0)));
            const float sp1 = fmaxf(cn1, 0.f) + log1pf(expf(-fabsf(cn1)));
            const float sp2 = fmaxf(cn2, 0.f) + log1pf(expf(-fabsf(cn2)));

            const float l0 = fmaf(n0, sp0 + NOISE_EPS, cg0);
            const float l1 = fmaf(n1, sp1 + NOISE_EPS, cg1);
            const float l2 = fmaf(n2, sp2 + NOISE_EPS, cg2);

            int   idx  = 0;
            float best = l0;
            if (l1 > best) { best = l1; idx = 1; }
            if (l2 > best) {            idx = 2; }
            out[t] = (float)idx;   // float32 output
        }
    }
}

extern "C" void kernel_launch(void* const* d_in, const int* in_sizes, int n_in,
                              void* d_out, int out_size)
{
    // Resolve inputs BY SIZE — robust to metadata.txt ordering.
    //   N*D = 67108864 -> input [N,D]
    //   N*E = 786432   -> noise [N,E]
    //   D*E = 768      -> w_gate (first), w_noise (second)
    const float* x   = nullptr;
    const float* wg  = nullptr;
    const float* wn  = nullptr;
    const float* nse = nullptr;

    for (int i = 0; i < n_in; ++i) {
        const long long sz = in_sizes[i];
        if (sz == (long long)GATE_N * GATE_D) {
            x = (const float*)d_in[i];
        } else if (sz == (long long)GATE_N * GATE_E) {
            nse = (const float*)d_in[i];
        } else if (sz == (long long)GATE_D * GATE_E) {
            if (!wg) wg = (const float*)d_in[i];
            else     wn = (const float*)d_in[i];
        }
    }

    float* out = (float*)d_out;
    (void)out_size;

    // 592 blocks x 256 threads = 4736 warps, ~55 tokens per warp
    // (amortizes the register weight preload).
    moe_gate_kernel<<<592, 256>>>(x, wg, wn, nse, out);
}

// round 8
// speedup vs baseline: 2.2801x; 2.2801x over previous
#include <cuda_runtime.h>
#include <cuda_bf16.h>

// MoE noisy top-1 gating, N=262144, D=256, E=3.
//   logits = x@wg + noise * (softplus(x@wn) + 0.2);  out[t] = argmax (as float)
//
// R7: 4 tokens per warp iteration.
//  - weights hoisted once (24 f32x2 regs), shared across the 4 tokens
//  - fma.rn.f32x2 packed FMAs: 24 per token
//  - token-fold reduction: 2 fold rounds (xor16, xor8) route each token's
//    partials into an 8-lane quadrant, then 3 butterfly rounds -> 7.5 SHFL/token
//  - softplus tail parallel across quadrants (lane 8q+e owns expert e of token q)
//  - one predicated noise LDG + one shfl.idx; one coalesced 4-lane STG

#define GATE_N 262144
#define GATE_D 256
#define GATE_E 3
#define NOISE_EPS 0.2f

__device__ __forceinline__ unsigned long long pk2(float lo, float hi) {
    unsigned long long r;
    asm("mov.b64 %0, {%1, %2};" : "=l"(r) : "f"(lo), "f"(hi));
    return r;
}
__device__ __forceinline__ void fma2(unsigned long long& acc,
                                     unsigned long long a,
                                     unsigned long long b) {
    asm("fma.rn.f32x2 %0, %1, %2, %0;" : "+l"(acc) : "l"(a), "l"(b));
}
__device__ __forceinline__ float unpk_sum(unsigned long long v) {
    float lo, hi;
    asm("mov.b64 {%0, %1}, %2;" : "=f"(lo), "=f"(hi) : "l"(v));
    return lo + hi;
}

__global__ __launch_bounds__(256, 2)
void moe_gate_kernel(const float* __restrict__ x,
                     const float* __restrict__ wg,
                     const float* __restrict__ wn,
                     const float* __restrict__ noise,
                     float* __restrict__ out)
{
    const int lane   = threadIdx.x & 31;
    const int gwarp  = (blockIdx.x * blockDim.x + threadIdx.x) >> 5;
    const int nwarps = (gridDim.x * blockDim.x) >> 5;

    // Lane owns dims {4l..4l+3} and {128+4l..128+4l+3} -> 4 f32x2 dim-pairs.
    // Hoist weights once: [pair][expert], gate then noise.
    unsigned long long wgp[4][3], wnp[4][3];
#pragma unroll
    for (int p = 0; p < 4; ++p) {
        const int d = (p < 2) ? (4 * lane + 2 * p) : (128 + 4 * lane + 2 * (p - 2));
#pragma unroll
        for (int e = 0; e < 3; ++e) {
            wgp[p][e] = pk2(__ldg(wg + d * 3 + e), __ldg(wg + (d + 1) * 3 + e));
            wnp[p][e] = pk2(__ldg(wn + d * 3 + e), __ldg(wn + (d + 1) * 3 + e));
        }
    }

    // Row = 256 floats = 64 ulonglong2 (each = 4 consecutive floats = 2 pairs).
    // Lane reads idx lane (dims 4l..4l+3) and idx 32+lane (dims 128+4l..).
    const ulonglong2* __restrict__ x2 = reinterpret_cast<const ulonglong2*>(x);

    const int quad = lane >> 3;        // which token this lane finalizes
    const int j    = lane & 7;         // role within quadrant (j<3 -> expert j)
    const int qbase = lane & 24;       // first lane of my quadrant

    for (int t0 = 4 * gwarp; t0 < GATE_N; t0 += 4 * nwarps) {
        // ---- front-batched loads: 8x LDG.128 (x) + 1 predicated LDG (noise) ----
        ulonglong2 xa[4], xb[4];
#pragma unroll
        for (int q = 0; q < 4; ++q) {
            xa[q] = x2[(size_t)(t0 + q) * 64 + lane];
            xb[q] = x2[(size_t)(t0 + q) * 64 + 32 + lane];
        }
        float nsraw = 0.f;
        if (lane < 12) nsraw = __ldg(noise + (size_t)t0 * 3 + lane);

        // ---- 96 packed FMAs: acc[q][e], e: 0-2 gate, 3-5 noise ----
        unsigned long long acc[4][6];
#pragma unroll
        for (int q = 0; q < 4; ++q) {
#pragma unroll
            for (int e = 0; e < 6; ++e) acc[q][e] = 0ull;
            const unsigned long long xp[4] = {xa[q].x, xa[q].y, xb[q].x, xb[q].y};
#pragma unroll
            for (int p = 0; p < 4; ++p) {
                fma2(acc[q][0], xp[p], wgp[p][0]);
                fma2(acc[q][1], xp[p], wgp[p][1]);
                fma2(acc[q][2], xp[p], wgp[p][2]);
                fma2(acc[q][3], xp[p], wnp[p][0]);
                fma2(acc[q][4], xp[p], wnp[p][1]);
                fma2(acc[q][5], xp[p], wnp[p][2]);
            }
        }

        // ---- unpack to scalars ----
        float P0[6], P1[6], P2[6], P3[6];
#pragma unroll
        for (int e = 0; e < 6; ++e) {
            P0[e] = unpk_sum(acc[0][e]);
            P1[e] = unpk_sum(acc[1][e]);
            P2[e] = unpk_sum(acc[2][e]);
            P3[e] = unpk_sum(acc[3][e]);
        }

        // ---- fold round 1 (xor 16): T0<->T2 and T1<->T3 ----
        const bool lo16 = (lane < 16);
        float U[6], W[6];
#pragma unroll
        for (int e = 0; e < 6; ++e) {
            const float u  = lo16 ? P0[e] : P2[e];
            const float uv = lo16 ? P2[e] : P0[e];
            U[e] = u + __shfl_xor_sync(0xFFFFFFFFu, uv, 16);
            const float w  = lo16 ? P1[e] : P3[e];
            const float wv = lo16 ? P3[e] : P1[e];
            W[e] = w + __shfl_xor_sync(0xFFFFFFFFu, wv, 16);
        }

        // ---- fold round 2 (xor 8): quadrant q ends with token q ----
        const bool lo8 = ((lane & 8) == 0);
        float R[6];
#pragma unroll
        for (int e = 0; e < 6; ++e) {
            const float r  = lo8 ? U[e] : W[e];
            const float rv = lo8 ? W[e] : U[e];
            R[e] = r + __shfl_xor_sync(0xFFFFFFFFu, rv, 8);
        }

        // ---- butterfly within 8-lane quadrants ----
#pragma unroll
        for (int off = 4; off > 0; off >>= 1) {
#pragma unroll
            for (int e = 0; e < 6; ++e)
                R[e] += __shfl_xor_sync(0xFFFFFFFFu, R[e], off);
        }

        // ---- tail: lane 8q+j (j<3) computes expert j's logit of token q ----
        const float nv = __shfl_sync(0xFFFFFFFFu, nsraw, 3 * quad + j);
        const float cg = (j == 1) ? R[1] : ((j == 2) ? R[2] : R[0]);
        const float cn = (j == 1) ? R[4] : ((j == 2) ? R[5] : R[3]);
        // stable softplus: max(x,0) + log1p(exp(-|x|))
        const float sp = fmaxf(cn, 0.f) + log1pf(expf(-fabsf(cn)));
        const float logit = fmaf(nv, sp + NOISE_EPS, cg);

        const float l1 = __shfl_sync(0xFFFFFFFFu, logit, qbase + 1);
        const float l2 = __shfl_sync(0xFFFFFFFFu, logit, qbase + 2);

        if (j == 0) {
            int   idx  = 0;
            float best = logit;          // expert 0
            if (l1 > best) { best = l1; idx = 1; }
            if (l2 > best) {            idx = 2; }
            out[t0 + quad] = (float)idx; // 4 lanes -> 16B coalesced store
        }
    }
}

extern "C" void kernel_launch(void* const* d_in, const int* in_sizes, int n_in,
                              void* d_out, int out_size)
{
    // Resolve inputs BY SIZE (robust to metadata ordering).
    //   N*D -> input, N*E -> noise, D*E -> w_gate (first), w_noise (second)
    const float* x   = nullptr;
    const float* wg  = nullptr;
    const float* wn  = nullptr;
    const float* nse = nullptr;

    for (int i = 0; i < n_in; ++i) {
        const long long sz = in_sizes[i];
        if (sz == (long long)GATE_N * GATE_D) {
            x = (const float*)d_in[i];
        } else if (sz == (long long)GATE_N * GATE_E) {
            nse = (const float*)d_in[i];
        } else if (sz == (long long)GATE_D * GATE_E) {
            if (!wg) wg = (const float*)d_in[i];
            else     wn = (const float*)d_in[i];
        }
    }

    float* out = (float*)d_out;
    (void)out_size;

    moe_gate_kernel<<<592, 256>>>(x, wg, wn, nse, out);
}

// round 9
// speedup vs baseline: 2.4671x; 1.0820x over previous
#include <cuda_runtime.h>
#include <cuda_bf16.h>

// MoE noisy top-1 gating, N=262144, D=256, E=3.
//   logits = x@wg + noise * (softplus(x@wn) + 0.2);  out[t] = argmax (as float)
//
// R8: R7 + software pipelining.
//  - per-token accumulator unpack (acc live range: 12 regs, not 48)
//  - next iteration's 8x LDG.128 + noise LDG issued after the FMA phase,
//    overlapping the ~250-cycle reduction/tail -> loads always in flight

#define GATE_N 262144
#define GATE_D 256
#define GATE_E 3
#define NOISE_EPS 0.2f

__device__ __forceinline__ unsigned long long pk2(float lo, float hi) {
    unsigned long long r;
    asm("mov.b64 %0, {%1, %2};" : "=l"(r) : "f"(lo), "f"(hi));
    return r;
}
__device__ __forceinline__ void fma2(unsigned long long& acc,
                                     unsigned long long a,
                                     unsigned long long b) {
    asm("fma.rn.f32x2 %0, %1, %2, %0;" : "+l"(acc) : "l"(a), "l"(b));
}
__device__ __forceinline__ float unpk_sum(unsigned long long v) {
    float lo, hi;
    asm("mov.b64 {%0, %1}, %2;" : "=f"(lo), "=f"(hi) : "l"(v));
    return lo + hi;
}

__global__ __launch_bounds__(256, 2)
void moe_gate_kernel(const float* __restrict__ x,
                     const float* __restrict__ wg,
                     const float* __restrict__ wn,
                     const float* __restrict__ noise,
                     float* __restrict__ out)
{
    const int lane   = threadIdx.x & 31;
    const int gwarp  = (blockIdx.x * blockDim.x + threadIdx.x) >> 5;
    const int nwarps = (gridDim.x * blockDim.x) >> 5;
    const int stride = 4 * nwarps;

    // Lane owns dims {4l..4l+3} and {128+4l..128+4l+3} -> 4 f32x2 dim-pairs.
    unsigned long long wgp[4][3], wnp[4][3];
#pragma unroll
    for (int p = 0; p < 4; ++p) {
        const int d = (p < 2) ? (4 * lane + 2 * p) : (128 + 4 * lane + 2 * (p - 2));
#pragma unroll
        for (int e = 0; e < 3; ++e) {
            wgp[p][e] = pk2(__ldg(wg + d * 3 + e), __ldg(wg + (d + 1) * 3 + e));
            wnp[p][e] = pk2(__ldg(wn + d * 3 + e), __ldg(wn + (d + 1) * 3 + e));
        }
    }

    // Row = 256 floats = 64 ulonglong2. Lane reads idx lane and 32+lane.
    const ulonglong2* __restrict__ x2 = reinterpret_cast<const ulonglong2*>(x);

    const int quad  = lane >> 3;   // token this lane finalizes
    const int j     = lane & 7;    // role in quadrant (j<3 -> expert j)
    const int qbase = lane & 24;   // first lane of my quadrant

    int t0 = 4 * gwarp;
    if (t0 >= GATE_N) return;

    // ---- prologue loads ----
    ulonglong2 xa[4], xb[4];
#pragma unroll
    for (int q = 0; q < 4; ++q) {
        xa[q] = x2[(size_t)(t0 + q) * 64 + lane];
        xb[q] = x2[(size_t)(t0 + q) * 64 + 32 + lane];
    }
    float nsraw = (lane < 12) ? __ldg(noise + (size_t)t0 * 3 + lane) : 0.f;

    while (t0 < GATE_N) {
        const int tn = t0 + stride;

        // ---- FMA phase: per token 24 fma2, then unpack (acc stays small) ----
        float P[4][6];
#pragma unroll
        for (int q = 0; q < 4; ++q) {
            unsigned long long a0 = 0, a1 = 0, a2 = 0, a3 = 0, a4 = 0, a5 = 0;
            const unsigned long long xp[4] = {xa[q].x, xa[q].y, xb[q].x, xb[q].y};
#pragma unroll
            for (int p = 0; p < 4; ++p) {
                fma2(a0, xp[p], wgp[p][0]);
                fma2(a1, xp[p], wgp[p][1]);
                fma2(a2, xp[p], wgp[p][2]);
                fma2(a3, xp[p], wnp[p][0]);
                fma2(a4, xp[p], wnp[p][1]);
                fma2(a5, xp[p], wnp[p][2]);
            }
            P[q][0] = unpk_sum(a0); P[q][1] = unpk_sum(a1); P[q][2] = unpk_sum(a2);
            P[q][3] = unpk_sum(a3); P[q][4] = unpk_sum(a4); P[q][5] = unpk_sum(a5);
        }

        // ---- prefetch next iteration (overlaps reduction + tail) ----
        float nsn = 0.f;
        if (tn < GATE_N) {
#pragma unroll
            for (int q = 0; q < 4; ++q) {
                xa[q] = x2[(size_t)(tn + q) * 64 + lane];
                xb[q] = x2[(size_t)(tn + q) * 64 + 32 + lane];
            }
            if (lane < 12) nsn = __ldg(noise + (size_t)tn * 3 + lane);
        }

        // ---- fold round 1 (xor 16): T0<->T2, T1<->T3 ----
        const bool lo16 = (lane < 16);
        float U[6], W[6];
#pragma unroll
        for (int e = 0; e < 6; ++e) {
            const float u  = lo16 ? P[0][e] : P[2][e];
            const float uv = lo16 ? P[2][e] : P[0][e];
            U[e] = u + __shfl_xor_sync(0xFFFFFFFFu, uv, 16);
            const float w  = lo16 ? P[1][e] : P[3][e];
            const float wv = lo16 ? P[3][e] : P[1][e];
            W[e] = w + __shfl_xor_sync(0xFFFFFFFFu, wv, 16);
        }

        // ---- fold round 2 (xor 8): quadrant q holds token q ----
        const bool lo8 = ((lane & 8) == 0);
        float R[6];
#pragma unroll
        for (int e = 0; e < 6; ++e) {
            const float r  = lo8 ? U[e] : W[e];
            const float rv = lo8 ? W[e] : U[e];
            R[e] = r + __shfl_xor_sync(0xFFFFFFFFu, rv, 8);
        }

        // ---- butterfly within 8-lane quadrants ----
#pragma unroll
        for (int off = 4; off > 0; off >>= 1) {
#pragma unroll
            for (int e = 0; e < 6; ++e)
                R[e] += __shfl_xor_sync(0xFFFFFFFFu, R[e], off);
        }

        // ---- tail: lane 8q+j (j<3) owns expert j of token q ----
        const float nv = __shfl_sync(0xFFFFFFFFu, nsraw, 3 * quad + j);
        const float cg = (j == 1) ? R[1] : ((j == 2) ? R[2] : R[0]);
        const float cn = (j == 1) ? R[4] : ((j == 2) ? R[5] : R[3]);
        const float sp = fmaxf(cn, 0.f) + log1pf(expf(-fabsf(cn)));
        const float logit = fmaf(nv, sp + NOISE_EPS, cg);

        const float l1 = __shfl_sync(0xFFFFFFFFu, logit, qbase + 1);
        const float l2 = __shfl_sync(0xFFFFFFFFu, logit, qbase + 2);

        if (j == 0) {
            int   idx  = 0;
            float best = logit;          // expert 0
            if (l1 > best) { best = l1; idx = 1; }
            if (l2 > best) {            idx = 2; }
            out[t0 + quad] = (float)idx; // 4 lanes, 16B coalesced
        }

        // ---- rotate pipeline ----
        nsraw = nsn;
        t0 = tn;
    }
}

extern "C" void kernel_launch(void* const* d_in, const int* in_sizes, int n_in,
                              void* d_out, int out_size)
{
    // Resolve inputs BY SIZE (robust to metadata ordering).
    //   N*D -> input, N*E -> noise, D*E -> w_gate (first), w_noise (second)
    const float* x   = nullptr;
    const float* wg  = nullptr;
    const float* wn  = nullptr;
    const float* nse = nullptr;

    for (int i = 0; i < n_in; ++i) {
        const long long sz = in_sizes[i];
        if (sz == (long long)GATE_N * GATE_D) {
            x = (const float*)d_in[i];
        } else if (sz == (long long)GATE_N * GATE_E) {
            nse = (const float*)d_in[i];
        } else if (sz == (long long)GATE_D * GATE_E) {
            if (!wg) wg = (const float*)d_in[i];
            else     wn = (const float*)d_in[i];
        }
    }

    float* out = (float*)d_out;
    (void)out_size;

    moe_gate_kernel<<<592, 256>>>(x, wg, wn, nse, out);
}